// round 4
// baseline (speedup 1.0000x reference)
#include <cuda_runtime.h>
#include <math.h>

// Problem constants
#define BB 32768
#define NA 9
#define RR 4

// Inter-block activation buffers (pre-BN), sanctioned __device__ scratch
__device__ float g_h0[BB * NA * 64];
__device__ float g_h1[BB * NA * 128];
__device__ float g_h2[BB * NA * 256];

// BN statistics / affine params per block (9 channels, padded to 16)
__device__ double g_sum[3][16];
__device__ double g_ssq[3][16];
__device__ float  g_scale[3][16];
__device__ float  g_shift[3][16];

__global__ void zero_stats_kernel() {
    int i = threadIdx.x;
    if (i < 48) {
        (&g_sum[0][0])[i] = 0.0;
        (&g_ssq[0][0])[i] = 0.0;
    }
}

// One RGCN block:
//   h_pre[b,n,:] = h@ws + sum_r (A_r h)@wr_r + bias
// Input h is: raw atom_feats (BLK==0) or BN+LeakyReLU of previous pre-acts.
// Writes h_pre to the block's global buffer and accumulates per-atom-channel
// sum / sumsq (training-mode BN stats over axes (batch, feature)).
template<int BLK, int DIN, int DOUT>
__global__ void rgcn_block_kernel(const float* __restrict__ atom,
                                  const float* __restrict__ adj,
                                  const float* __restrict__ ws,
                                  const float* __restrict__ wr,
                                  const float* __restrict__ bias) {
    constexpr int TB = 4;                       // molecules per CTA
    constexpr int BD = (DIN < 16) ? DIN : 16;   // K-panel depth
    constexpr int CP = DOUT / 64;               // cols per thread

    extern __shared__ float sm[];
    float* hs   = sm;                           // [TB][9][DIN] input features
    float* vb   = hs + TB * NA * DIN;           // [TB][9][DIN] A_r h scratch
    float* adjS = vb + TB * NA * DIN;           // [TB][4][9][9]
    float* wp   = adjS + TB * RR * 81;          // [BD][DOUT] W panel

    const int tid = threadIdx.x;
    const int tx  = tid & 63;    // column group
    const int ty  = tid >> 6;    // molecule within CTA (warp spans tx only)
    const int b0  = blockIdx.x * TB;

    // ---- load adjacency tile (contiguous) ----
    {
        const float* src = adj + (size_t)b0 * RR * 81;
        for (int i = tid; i < TB * RR * 81; i += 256) adjS[i] = src[i];
    }
    // ---- load input features (apply BN + LeakyReLU of previous block) ----
    if (BLK == 0) {
        const float* src = atom + (size_t)b0 * NA * DIN;
        for (int i = tid; i < TB * NA * DIN; i += 256) hs[i] = src[i];
    } else {
        const float* src = (BLK == 1 ? g_h0 : g_h1) + (size_t)b0 * NA * DIN;
        for (int i = tid; i < TB * NA * DIN; i += 256) {
            int n = (i / DIN) % NA;
            float x = src[i];
            float y = g_scale[BLK - 1][n] * x + g_shift[BLK - 1][n];
            hs[i] = (y > 0.f) ? y : 0.2f * y;
        }
    }
    __syncthreads();

    float acc[NA][CP];
#pragma unroll
    for (int n = 0; n < NA; ++n)
#pragma unroll
        for (int c = 0; c < CP; ++c) acc[n][c] = 0.f;

    // ---- 5 sources: s=0 self (hs @ ws), s=1..4 relation ((A_r h) @ wr_r) ----
    for (int s = 0; s <= RR; ++s) {
        const float* xs;
        if (s == 0) {
            xs = hs;
        } else {
            __syncthreads();   // previous GEMM pass finished reading vb
            const int r = s - 1;
            for (int i = tid; i < TB * NA * DIN; i += 256) {
                int bl = i / (NA * DIN);
                int n  = (i / DIN) % NA;
                int d  = i - (bl * NA + n) * DIN;
                const float* arow = &adjS[((bl * RR + r) * NA + n) * NA];
                const float* hcol = &hs[bl * NA * DIN + d];
                float a = 0.f;
#pragma unroll
                for (int m = 0; m < NA; ++m) a += arow[m] * hcol[m * DIN];
                vb[i] = a;
            }
            xs = vb;
        }
        const float* wbase = (s == 0) ? ws : (wr + (size_t)(s - 1) * DIN * DOUT);

        for (int dt = 0; dt < DIN; dt += BD) {
            __syncthreads();   // previous panel consumed (also publishes vb)
            {
                const float4* wsrc = (const float4*)(wbase + (size_t)dt * DOUT);
                float4* wdst = (float4*)wp;
                for (int i = tid; i < BD * DOUT / 4; i += 256) wdst[i] = wsrc[i];
            }
            __syncthreads();

            const float* xb = xs + (ty * NA) * DIN + dt;
#pragma unroll 4
            for (int d = 0; d < BD; ++d) {
                float xv[NA];
#pragma unroll
                for (int n = 0; n < NA; ++n) xv[n] = xb[n * DIN + d];  // warp broadcast
                const float* wrow = &wp[d * DOUT + tx * CP];
                float wv[CP];
                if (CP == 4) {
                    float4 t = *(const float4*)wrow;
                    wv[0] = t.x; wv[1] = t.y; wv[2] = t.z; wv[3] = t.w;
                } else if (CP == 2) {
                    float2 t = *(const float2*)wrow;
                    wv[0] = t.x; wv[1] = t.y;
                } else {
                    wv[0] = wrow[0];
                }
#pragma unroll
                for (int n = 0; n < NA; ++n)
#pragma unroll
                    for (int c = 0; c < CP; ++c) acc[n][c] += xv[n] * wv[c];
            }
        }
    }

    // ---- bias, store pre-acts, per-channel stats ----
    float bb[CP];
#pragma unroll
    for (int c = 0; c < CP; ++c) bb[c] = bias[tx * CP + c];

    float* hout = (BLK == 0) ? g_h0 : (BLK == 1) ? g_h1 : g_h2;
    float sn[NA], qn[NA];
#pragma unroll
    for (int n = 0; n < NA; ++n) {
        float v[CP];
        float s1 = 0.f, s2 = 0.f;
#pragma unroll
        for (int c = 0; c < CP; ++c) {
            v[c] = acc[n][c] + bb[c];
            s1 += v[c];
            s2 += v[c] * v[c];
        }
        sn[n] = s1; qn[n] = s2;
        float* dst = hout + ((size_t)(b0 + ty) * NA + n) * DOUT + tx * CP;
        if (CP == 4)      *(float4*)dst = make_float4(v[0], v[1], v[2], v[3]);
        else if (CP == 2) *(float2*)dst = make_float2(v[0], v[1]);
        else              dst[0] = v[0];
    }

    // warp reduction then CTA reduction of stats
#pragma unroll
    for (int n = 0; n < NA; ++n) {
#pragma unroll
        for (int off = 16; off > 0; off >>= 1) {
            sn[n] += __shfl_down_sync(0xffffffffu, sn[n], off);
            qn[n] += __shfl_down_sync(0xffffffffu, qn[n], off);
        }
    }
    __syncthreads();                 // adjS no longer needed; reuse as scratch
    float* redS = adjS;              // [9][8]
    float* redQ = adjS + NA * 8;     // [9][8]
    const int lane = tid & 31, wrp = tid >> 5;
    if (lane == 0) {
#pragma unroll
        for (int n = 0; n < NA; ++n) { redS[n * 8 + wrp] = sn[n]; redQ[n * 8 + wrp] = qn[n]; }
    }
    __syncthreads();
    if (tid < NA) {
        float a = 0.f, q = 0.f;
#pragma unroll
        for (int w = 0; w < 8; ++w) { a += redS[tid * 8 + w]; q += redQ[tid * 8 + w]; }
        atomicAdd(&g_sum[BLK][tid], (double)a);
        atomicAdd(&g_ssq[BLK][tid], (double)q);
    }
}

template<int BLK, int DOUT>
__global__ void finalize_kernel(const float* __restrict__ gamma,
                                const float* __restrict__ beta) {
    int n = threadIdx.x;
    if (n < NA) {
        double cnt  = (double)BB * (double)DOUT;
        double mean = g_sum[BLK][n] / cnt;
        double var  = g_ssq[BLK][n] / cnt - mean * mean;
        double inv  = 1.0 / sqrt(var + 1e-5);
        double sc   = (double)gamma[n] * inv;
        g_scale[BLK][n] = (float)sc;
        g_shift[BLK][n] = (float)((double)beta[n] - mean * sc);
    }
}

// Readout: BN2 + LeakyReLU on the fly, masked sum over atoms, dot with fc_w.
__global__ void readout_kernel(const float* __restrict__ mask,
                               const float* __restrict__ fcw,
                               const float* __restrict__ fcb,
                               float* __restrict__ out) {
    constexpr int DOUT = 256;
    int warp = (blockIdx.x * blockDim.x + threadIdx.x) >> 5;
    int lane = threadIdx.x & 31;
    if (warp >= BB) return;
    int b = warp;

    float wreg[8];
#pragma unroll
    for (int i = 0; i < 8; ++i) wreg[i] = fcw[lane + 32 * i];

    const float* hb = g_h2 + (size_t)b * NA * DOUT;
    float acc = 0.f;
#pragma unroll
    for (int n = 0; n < NA; ++n) {
        float sc = g_scale[2][n], sh = g_shift[2][n];
        float m  = mask[b * NA + n];
        float pa = 0.f;
#pragma unroll
        for (int i = 0; i < 8; ++i) {
            float y = sc * hb[n * DOUT + lane + 32 * i] + sh;
            y = (y > 0.f) ? y : 0.2f * y;
            pa += y * wreg[i];
        }
        acc += m * pa;
    }
#pragma unroll
    for (int off = 16; off > 0; off >>= 1)
        acc += __shfl_down_sync(0xffffffffu, acc, off);
    if (lane == 0) out[b] = acc + fcb[0];
}

static constexpr int smem_bytes(int din, int dout) {
    int bd = (din < 16) ? din : 16;
    return (2 * 4 * NA * din + 4 * RR * 81 + bd * dout) * 4;
}

extern "C" void kernel_launch(void* const* d_in, const int* in_sizes, int n_in,
                              void* d_out, int out_size) {
    (void)in_sizes; (void)n_in; (void)out_size;
    const float* atom = (const float*)d_in[0];
    const float* adj  = (const float*)d_in[1];
    const float* mask = (const float*)d_in[2];
    const float* ws0 = (const float*)d_in[3];
    const float* wr0 = (const float*)d_in[4];
    const float* b0  = (const float*)d_in[5];
    const float* g0  = (const float*)d_in[6];
    const float* be0 = (const float*)d_in[7];
    const float* ws1 = (const float*)d_in[8];
    const float* wr1 = (const float*)d_in[9];
    const float* b1  = (const float*)d_in[10];
    const float* g1  = (const float*)d_in[11];
    const float* be1 = (const float*)d_in[12];
    const float* ws2 = (const float*)d_in[13];
    const float* wr2 = (const float*)d_in[14];
    const float* b2  = (const float*)d_in[15];
    const float* g2  = (const float*)d_in[16];
    const float* be2 = (const float*)d_in[17];
    const float* fcw = (const float*)d_in[18];
    const float* fcb = (const float*)d_in[19];
    float* out = (float*)d_out;

    constexpr int S0 = smem_bytes(5, 64);
    constexpr int S1 = smem_bytes(64, 128);
    constexpr int S2 = smem_bytes(128, 256);

    cudaFuncSetAttribute((const void*)rgcn_block_kernel<0, 5, 64>,
                         cudaFuncAttributeMaxDynamicSharedMemorySize, S0);
    cudaFuncSetAttribute((const void*)rgcn_block_kernel<1, 64, 128>,
                         cudaFuncAttributeMaxDynamicSharedMemorySize, S1);
    cudaFuncSetAttribute((const void*)rgcn_block_kernel<2, 128, 256>,
                         cudaFuncAttributeMaxDynamicSharedMemorySize, S2);

    const int grid = BB / 4;   // TB = 4

    zero_stats_kernel<<<1, 64>>>();
    rgcn_block_kernel<0, 5, 64><<<grid, 256, S0>>>(atom, adj, ws0, wr0, b0);
    finalize_kernel<0, 64><<<1, 32>>>(g0, be0);
    rgcn_block_kernel<1, 64, 128><<<grid, 256, S1>>>(atom, adj, ws1, wr1, b1);
    finalize_kernel<1, 128><<<1, 32>>>(g1, be1);
    rgcn_block_kernel<2, 128, 256><<<grid, 256, S2>>>(atom, adj, ws2, wr2, b2);
    finalize_kernel<2, 256><<<1, 32>>>(g2, be2);
    readout_kernel<<<BB / 8, 256>>>(mask, fcw, fcb, out);
}

// round 6
// speedup vs baseline: 1.0000x; 1.0000x over previous
#include <cuda_runtime.h>
#include <math.h>

// Problem constants
#define BB 32768
#define NA 9
#define RR 4

// Inter-block activation buffers (pre-BN), sanctioned __device__ scratch
__device__ float g_h0[BB * NA * 64];
__device__ float g_h1[BB * NA * 128];
__device__ float g_h2[BB * NA * 256];

// BN statistics / affine params per block (9 channels, padded to 16)
__device__ double g_sum[3][16];
__device__ double g_ssq[3][16];
__device__ float  g_scale[3][16];
__device__ float  g_shift[3][16];

__global__ void zero_stats_kernel() {
    int i = threadIdx.x;
    if (i < 48) {
        (&g_sum[0][0])[i] = 0.0;
        (&g_ssq[0][0])[i] = 0.0;
    }
}

// One RGCN block:
//   h_pre[b,n,:] = h@ws + sum_r (A_r h)@wr_r + bias
// Input h is: raw atom_feats (BLK==0) or BN+LeakyReLU of previous pre-acts.
// Writes h_pre to the block's global buffer and accumulates per-atom-channel
// sum / sumsq (training-mode BN stats over axes (batch, feature)).
template<int BLK, int DIN, int DOUT>
__global__ void rgcn_block_kernel(const float* __restrict__ atom,
                                  const float* __restrict__ adj,
                                  const float* __restrict__ ws,
                                  const float* __restrict__ wr,
                                  const float* __restrict__ bias) {
    constexpr int TB = 4;                       // molecules per CTA
    constexpr int BD = (DIN < 16) ? DIN : 16;   // K-panel depth
    constexpr int CP = DOUT / 64;               // cols per thread

    extern __shared__ float sm[];
    float* hs   = sm;                           // [TB][9][DIN] input features
    float* vb   = hs + TB * NA * DIN;           // [TB][9][DIN] A_r h scratch
    float* adjS = vb + TB * NA * DIN;           // [TB][4][9][9]
    float* wp   = adjS + TB * RR * 81;          // [BD][DOUT] W panel

    const int tid = threadIdx.x;
    const int tx  = tid & 63;    // column group
    const int ty  = tid >> 6;    // molecule within CTA (warp spans tx only)
    const int b0  = blockIdx.x * TB;

    // ---- load adjacency tile (contiguous) ----
    {
        const float* src = adj + (size_t)b0 * RR * 81;
        for (int i = tid; i < TB * RR * 81; i += 256) adjS[i] = src[i];
    }
    // ---- load input features (apply BN + LeakyReLU of previous block) ----
    if (BLK == 0) {
        const float* src = atom + (size_t)b0 * NA * DIN;
        for (int i = tid; i < TB * NA * DIN; i += 256) hs[i] = src[i];
    } else {
        const float* src = (BLK == 1 ? g_h0 : g_h1) + (size_t)b0 * NA * DIN;
        for (int i = tid; i < TB * NA * DIN; i += 256) {
            int n = (i / DIN) % NA;
            float x = src[i];
            float y = g_scale[BLK - 1][n] * x + g_shift[BLK - 1][n];
            hs[i] = (y > 0.f) ? y : 0.2f * y;
        }
    }
    __syncthreads();

    float acc[NA][CP];
#pragma unroll
    for (int n = 0; n < NA; ++n)
#pragma unroll
        for (int c = 0; c < CP; ++c) acc[n][c] = 0.f;

    // ---- 5 sources: s=0 self (hs @ ws), s=1..4 relation ((A_r h) @ wr_r) ----
    for (int s = 0; s <= RR; ++s) {
        const float* xs;
        if (s == 0) {
            xs = hs;
        } else {
            __syncthreads();   // previous GEMM pass finished reading vb
            const int r = s - 1;
            for (int i = tid; i < TB * NA * DIN; i += 256) {
                int bl = i / (NA * DIN);
                int n  = (i / DIN) % NA;
                int d  = i - (bl * NA + n) * DIN;
                const float* arow = &adjS[((bl * RR + r) * NA + n) * NA];
                const float* hcol = &hs[bl * NA * DIN + d];
                float a = 0.f;
#pragma unroll
                for (int m = 0; m < NA; ++m) a += arow[m] * hcol[m * DIN];
                vb[i] = a;
            }
            xs = vb;
        }
        const float* wbase = (s == 0) ? ws : (wr + (size_t)(s - 1) * DIN * DOUT);

        for (int dt = 0; dt < DIN; dt += BD) {
            __syncthreads();   // previous panel consumed (also publishes vb)
            {
                const float4* wsrc = (const float4*)(wbase + (size_t)dt * DOUT);
                float4* wdst = (float4*)wp;
                for (int i = tid; i < BD * DOUT / 4; i += 256) wdst[i] = wsrc[i];
            }
            __syncthreads();

            const float* xb = xs + (ty * NA) * DIN + dt;
#pragma unroll 4
            for (int d = 0; d < BD; ++d) {
                float xv[NA];
#pragma unroll
                for (int n = 0; n < NA; ++n) xv[n] = xb[n * DIN + d];  // warp broadcast
                const float* wrow = &wp[d * DOUT + tx * CP];
                float wv[CP];
                if (CP == 4) {
                    float4 t = *(const float4*)wrow;
                    wv[0] = t.x; wv[1] = t.y; wv[2] = t.z; wv[3] = t.w;
                } else if (CP == 2) {
                    float2 t = *(const float2*)wrow;
                    wv[0] = t.x; wv[1] = t.y;
                } else {
                    wv[0] = wrow[0];
                }
#pragma unroll
                for (int n = 0; n < NA; ++n)
#pragma unroll
                    for (int c = 0; c < CP; ++c) acc[n][c] += xv[n] * wv[c];
            }
        }
    }

    // ---- bias, store pre-acts, per-channel stats ----
    float bb[CP];
#pragma unroll
    for (int c = 0; c < CP; ++c) bb[c] = bias[tx * CP + c];

    float* hout = (BLK == 0) ? g_h0 : (BLK == 1) ? g_h1 : g_h2;
    float sn[NA], qn[NA];
#pragma unroll
    for (int n = 0; n < NA; ++n) {
        float v[CP];
        float s1 = 0.f, s2 = 0.f;
#pragma unroll
        for (int c = 0; c < CP; ++c) {
            v[c] = acc[n][c] + bb[c];
            s1 += v[c];
            s2 += v[c] * v[c];
        }
        sn[n] = s1; qn[n] = s2;
        float* dst = hout + ((size_t)(b0 + ty) * NA + n) * DOUT + tx * CP;
        if (CP == 4)      *(float4*)dst = make_float4(v[0], v[1], v[2], v[3]);
        else if (CP == 2) *(float2*)dst = make_float2(v[0], v[1]);
        else              dst[0] = v[0];
    }

    // warp reduction then CTA reduction of stats
#pragma unroll
    for (int n = 0; n < NA; ++n) {
#pragma unroll
        for (int off = 16; off > 0; off >>= 1) {
            sn[n] += __shfl_down_sync(0xffffffffu, sn[n], off);
            qn[n] += __shfl_down_sync(0xffffffffu, qn[n], off);
        }
    }
    __syncthreads();                 // adjS no longer needed; reuse as scratch
    float* redS = adjS;              // [9][8]
    float* redQ = adjS + NA * 8;     // [9][8]
    const int lane = tid & 31, wrp = tid >> 5;
    if (lane == 0) {
#pragma unroll
        for (int n = 0; n < NA; ++n) { redS[n * 8 + wrp] = sn[n]; redQ[n * 8 + wrp] = qn[n]; }
    }
    __syncthreads();
    if (tid < NA) {
        float a = 0.f, q = 0.f;
#pragma unroll
        for (int w = 0; w < 8; ++w) { a += redS[tid * 8 + w]; q += redQ[tid * 8 + w]; }
        atomicAdd(&g_sum[BLK][tid], (double)a);
        atomicAdd(&g_ssq[BLK][tid], (double)q);
    }
}

template<int BLK, int DOUT>
__global__ void finalize_kernel(const float* __restrict__ gamma,
                                const float* __restrict__ beta) {
    int n = threadIdx.x;
    if (n < NA) {
        double cnt  = (double)BB * (double)DOUT;
        double mean = g_sum[BLK][n] / cnt;
        double var  = g_ssq[BLK][n] / cnt - mean * mean;
        double inv  = 1.0 / sqrt(var + 1e-5);
        double sc   = (double)gamma[n] * inv;
        g_scale[BLK][n] = (float)sc;
        g_shift[BLK][n] = (float)((double)beta[n] - mean * sc);
    }
}

// Readout: BN2 + LeakyReLU on the fly, masked sum over atoms, dot with fc_w.
__global__ void readout_kernel(const float* __restrict__ mask,
                               const float* __restrict__ fcw,
                               const float* __restrict__ fcb,
                               float* __restrict__ out) {
    constexpr int DOUT = 256;
    int warp = (blockIdx.x * blockDim.x + threadIdx.x) >> 5;
    int lane = threadIdx.x & 31;
    if (warp >= BB) return;
    int b = warp;

    float wreg[8];
#pragma unroll
    for (int i = 0; i < 8; ++i) wreg[i] = fcw[lane + 32 * i];

    const float* hb = g_h2 + (size_t)b * NA * DOUT;
    float acc = 0.f;
#pragma unroll
    for (int n = 0; n < NA; ++n) {
        float sc = g_scale[2][n], sh = g_shift[2][n];
        float m  = mask[b * NA + n];
        float pa = 0.f;
#pragma unroll
        for (int i = 0; i < 8; ++i) {
            float y = sc * hb[n * DOUT + lane + 32 * i] + sh;
            y = (y > 0.f) ? y : 0.2f * y;
            pa += y * wreg[i];
        }
        acc += m * pa;
    }
#pragma unroll
    for (int off = 16; off > 0; off >>= 1)
        acc += __shfl_down_sync(0xffffffffu, acc, off);
    if (lane == 0) out[b] = acc + fcb[0];
}

static constexpr int smem_bytes(int din, int dout) {
    int bd = (din < 16) ? din : 16;
    return (2 * 4 * NA * din + 4 * RR * 81 + bd * dout) * 4;
}

extern "C" void kernel_launch(void* const* d_in, const int* in_sizes, int n_in,
                              void* d_out, int out_size) {
    (void)in_sizes; (void)n_in; (void)out_size;
    const float* atom = (const float*)d_in[0];
    const float* adj  = (const float*)d_in[1];
    const float* mask = (const float*)d_in[2];
    const float* ws0 = (const float*)d_in[3];
    const float* wr0 = (const float*)d_in[4];
    const float* b0  = (const float*)d_in[5];
    const float* g0  = (const float*)d_in[6];
    const float* be0 = (const float*)d_in[7];
    const float* ws1 = (const float*)d_in[8];
    const float* wr1 = (const float*)d_in[9];
    const float* b1  = (const float*)d_in[10];
    const float* g1  = (const float*)d_in[11];
    const float* be1 = (const float*)d_in[12];
    const float* ws2 = (const float*)d_in[13];
    const float* wr2 = (const float*)d_in[14];
    const float* b2  = (const float*)d_in[15];
    const float* g2  = (const float*)d_in[16];
    const float* be2 = (const float*)d_in[17];
    const float* fcw = (const float*)d_in[18];
    const float* fcb = (const float*)d_in[19];
    float* out = (float*)d_out;

    constexpr int S0 = smem_bytes(5, 64);
    constexpr int S1 = smem_bytes(64, 128);
    constexpr int S2 = smem_bytes(128, 256);

    cudaFuncSetAttribute((const void*)rgcn_block_kernel<0, 5, 64>,
                         cudaFuncAttributeMaxDynamicSharedMemorySize, S0);
    cudaFuncSetAttribute((const void*)rgcn_block_kernel<1, 64, 128>,
                         cudaFuncAttributeMaxDynamicSharedMemorySize, S1);
    cudaFuncSetAttribute((const void*)rgcn_block_kernel<2, 128, 256>,
                         cudaFuncAttributeMaxDynamicSharedMemorySize, S2);

    const int grid = BB / 4;   // TB = 4

    zero_stats_kernel<<<1, 64>>>();
    rgcn_block_kernel<0, 5, 64><<<grid, 256, S0>>>(atom, adj, ws0, wr0, b0);
    finalize_kernel<0, 64><<<1, 32>>>(g0, be0);
    rgcn_block_kernel<1, 64, 128><<<grid, 256, S1>>>(atom, adj, ws1, wr1, b1);
    finalize_kernel<1, 128><<<1, 32>>>(g1, be1);
    rgcn_block_kernel<2, 128, 256><<<grid, 256, S2>>>(atom, adj, ws2, wr2, b2);
    finalize_kernel<2, 256><<<1, 32>>>(g2, be2);
    readout_kernel<<<BB / 8, 256>>>(mask, fcw, fcb, out);
}